// round 1
// baseline (speedup 1.0000x reference)
#include <cuda_runtime.h>

#define NPOS 4096
#define CH   256
#define BATCH 8

// Scratch for q/k/v in (B, N, C) layout (c contiguous). 3 x 32 MB.
__device__ float g_q[BATCH * NPOS * CH];
__device__ float g_k[BATCH * NPOS * CH];
__device__ float g_v[BATCH * NPOS * CH];

// ---------------------------------------------------------------------------
// Kernel 1: fused QKV projection.
// q[b,n,o] = sum_c Wq[o,c] * x[b,c,n] + bq[o]   (same for k, v)
// Grid: (N/64, C/64, B). Block: 256 threads -> 64n x 64o tile for q,k,v.
// ---------------------------------------------------------------------------
__global__ __launch_bounds__(256, 2) void qkv_kernel(
    const float* __restrict__ x,
    const float* __restrict__ Wq, const float* __restrict__ bq,
    const float* __restrict__ Wk, const float* __restrict__ bk,
    const float* __restrict__ Wv, const float* __restrict__ bv)
{
    extern __shared__ float sm[];
    float* xs  = sm;                 // [64 n][68]  (c within chunk)
    float* wqs = xs  + 64 * 68;      // [64 o][68]
    float* wks = wqs + 64 * 68;
    float* wvs = wks + 64 * 68;

    const int tid = threadIdx.x;
    const int tx = tid & 15, ty = tid >> 4;
    const int ntile = blockIdx.x * 64;
    const int otile = blockIdx.y * 64;
    const int b = blockIdx.z;

    float aq[4][4], ak[4][4], av[4][4];
#pragma unroll
    for (int j = 0; j < 4; j++) {
        const int o = otile + tx + 16 * j;
        const float vbq = bq[o], vbk = bk[o], vbv = bv[o];
#pragma unroll
        for (int i = 0; i < 4; i++) { aq[i][j] = vbq; ak[i][j] = vbk; av[i][j] = vbv; }
    }

    for (int cc = 0; cc < CH / 64; cc++) {
        __syncthreads();
        // x tile, transposed into [n][c] layout
#pragma unroll
        for (int it = 0; it < 4; it++) {
            const int lin = tid + it * 256;          // 1024 float4s
            const int c_l = lin >> 4;                // 0..63
            const int n0  = (lin & 15) * 4;
            const float4 t = *(const float4*)&x[((size_t)(b * CH + cc * 64 + c_l)) * NPOS + ntile + n0];
            xs[(n0 + 0) * 68 + c_l] = t.x;
            xs[(n0 + 1) * 68 + c_l] = t.y;
            xs[(n0 + 2) * 68 + c_l] = t.z;
            xs[(n0 + 3) * 68 + c_l] = t.w;
        }
        // W tiles (no transpose needed, [o][c])
#pragma unroll
        for (int it = 0; it < 4; it++) {
            const int lin = tid + it * 256;
            const int o_l = lin >> 4;
            const int c4  = (lin & 15) * 4;
            const size_t gofs = (size_t)(otile + o_l) * CH + cc * 64 + c4;
            *(float4*)&wqs[o_l * 68 + c4] = *(const float4*)&Wq[gofs];
            *(float4*)&wks[o_l * 68 + c4] = *(const float4*)&Wk[gofs];
            *(float4*)&wvs[o_l * 68 + c4] = *(const float4*)&Wv[gofs];
        }
        __syncthreads();

#pragma unroll 4
        for (int c0 = 0; c0 < 64; c0 += 4) {
            float4 a4[4];
#pragma unroll
            for (int i = 0; i < 4; i++)
                a4[i] = *(const float4*)&xs[(ty * 4 + i) * 68 + c0];
#pragma unroll
            for (int j = 0; j < 4; j++) {
                const int orow = (tx + 16 * j) * 68 + c0;
                float4 w4;
                w4 = *(const float4*)&wqs[orow];
#pragma unroll
                for (int i = 0; i < 4; i++)
                    aq[i][j] += a4[i].x * w4.x + a4[i].y * w4.y + a4[i].z * w4.z + a4[i].w * w4.w;
                w4 = *(const float4*)&wks[orow];
#pragma unroll
                for (int i = 0; i < 4; i++)
                    ak[i][j] += a4[i].x * w4.x + a4[i].y * w4.y + a4[i].z * w4.z + a4[i].w * w4.w;
                w4 = *(const float4*)&wvs[orow];
#pragma unroll
                for (int i = 0; i < 4; i++)
                    av[i][j] += a4[i].x * w4.x + a4[i].y * w4.y + a4[i].z * w4.z + a4[i].w * w4.w;
            }
        }
    }

    // store to (B, N, C) scratch
#pragma unroll
    for (int i = 0; i < 4; i++) {
        const size_t base = ((size_t)b * NPOS + ntile + ty * 4 + i) * CH + otile + tx;
#pragma unroll
        for (int j = 0; j < 4; j++) {
            g_q[base + 16 * j] = aq[i][j];
            g_k[base + 16 * j] = ak[i][j];
            g_v[base + 16 * j] = av[i][j];
        }
    }
}

// ---------------------------------------------------------------------------
// Kernel 2: flash attention + epilogue.
// Grid: (N/64, B). Block 256 threads. One 64-query tile per block.
// energy[i,j] = <q_i, k_j>; online softmax over all 4096 keys (tiles of 64);
// out = gamma * (P V) / (l * sqrt(N)) + x.
// ---------------------------------------------------------------------------
__global__ __launch_bounds__(256, 1) void attn_kernel(
    const float* __restrict__ x,
    const float* __restrict__ gamma,
    float* __restrict__ out)
{
    extern __shared__ float sm[];
    float* q_s = sm;                  // [64][260]
    float* k_s = q_s + 64 * 260;      // [64][260]
    float* v_s = k_s + 64 * 260;      // [64][260]
    float* p_s = v_s + 64 * 260;      // [64][64]

    const int tid = threadIdx.x;
    const int tx = tid & 15, ty = tid >> 4;
    const int n0 = blockIdx.x * 64;
    const int b = blockIdx.y;

    // load q tile (row-major [n][c], c contiguous -> direct float4 copy)
    {
        const float* qg = &g_q[((size_t)b * NPOS + n0) * CH];
#pragma unroll
        for (int it = 0; it < 16; it++) {
            const int lin = tid + it * 256;   // 4096 float4s
            const int r = lin >> 6;
            const int c4 = (lin & 63) * 4;
            *(float4*)&q_s[r * 260 + c4] = *(const float4*)&qg[r * CH + c4];
        }
    }

    float acc[4][16];
#pragma unroll
    for (int i = 0; i < 4; i++)
#pragma unroll
        for (int j = 0; j < 16; j++) acc[i][j] = 0.f;
    float m_i[4] = {-1e30f, -1e30f, -1e30f, -1e30f};
    float l_i[4] = {0.f, 0.f, 0.f, 0.f};

    for (int kt = 0; kt < NPOS / 64; kt++) {
        __syncthreads();   // previous iteration's smem consumption done
        {
            const float* kg = &g_k[((size_t)b * NPOS + kt * 64) * CH];
            const float* vg = &g_v[((size_t)b * NPOS + kt * 64) * CH];
#pragma unroll
            for (int it = 0; it < 16; it++) {
                const int lin = tid + it * 256;
                const int r = lin >> 6;
                const int c4 = (lin & 63) * 4;
                *(float4*)&k_s[r * 260 + c4] = *(const float4*)&kg[r * CH + c4];
                *(float4*)&v_s[r * 260 + c4] = *(const float4*)&vg[r * CH + c4];
            }
        }
        __syncthreads();

        // energy tile: rows ty*4+i, cols tx+16*j (conflict-free LDS.128)
        float e[4][4];
#pragma unroll
        for (int i = 0; i < 4; i++)
#pragma unroll
            for (int j = 0; j < 4; j++) e[i][j] = 0.f;

#pragma unroll 4
        for (int c0 = 0; c0 < CH; c0 += 4) {
            float4 a4[4], b4[4];
#pragma unroll
            for (int i = 0; i < 4; i++)
                a4[i] = *(const float4*)&q_s[(ty * 4 + i) * 260 + c0];
#pragma unroll
            for (int j = 0; j < 4; j++)
                b4[j] = *(const float4*)&k_s[(tx + 16 * j) * 260 + c0];
#pragma unroll
            for (int i = 0; i < 4; i++)
#pragma unroll
                for (int j = 0; j < 4; j++)
                    e[i][j] += a4[i].x * b4[j].x + a4[i].y * b4[j].y +
                               a4[i].z * b4[j].z + a4[i].w * b4[j].w;
        }

        // online softmax per query row; tx-group of 16 lanes holds one row set
#pragma unroll
        for (int i = 0; i < 4; i++) {
            float mt = fmaxf(fmaxf(e[i][0], e[i][1]), fmaxf(e[i][2], e[i][3]));
            mt = fmaxf(mt, __shfl_xor_sync(0xffffffffu, mt, 1));
            mt = fmaxf(mt, __shfl_xor_sync(0xffffffffu, mt, 2));
            mt = fmaxf(mt, __shfl_xor_sync(0xffffffffu, mt, 4));
            mt = fmaxf(mt, __shfl_xor_sync(0xffffffffu, mt, 8));
            const float mn = fmaxf(m_i[i], mt);
            const float scale = __expf(m_i[i] - mn);
            m_i[i] = mn;
            float ps = 0.f;
#pragma unroll
            for (int j = 0; j < 4; j++) {
                const float p = __expf(e[i][j] - mn);
                e[i][j] = p;
                ps += p;
            }
            ps += __shfl_xor_sync(0xffffffffu, ps, 1);
            ps += __shfl_xor_sync(0xffffffffu, ps, 2);
            ps += __shfl_xor_sync(0xffffffffu, ps, 4);
            ps += __shfl_xor_sync(0xffffffffu, ps, 8);
            l_i[i] = l_i[i] * scale + ps;
#pragma unroll
            for (int j2 = 0; j2 < 16; j2++) acc[i][j2] *= scale;
#pragma unroll
            for (int j = 0; j < 4; j++)
                p_s[(ty * 4 + i) * 64 + tx + 16 * j] = e[i][j];
        }
        __syncthreads();

        // PV: acc[i][j2] += sum_j p[row_i][j] * v[j][tx+16*j2]
#pragma unroll 2
        for (int j = 0; j < 64; j++) {
            const float pa0 = p_s[(ty * 4 + 0) * 64 + j];
            const float pa1 = p_s[(ty * 4 + 1) * 64 + j];
            const float pa2 = p_s[(ty * 4 + 2) * 64 + j];
            const float pa3 = p_s[(ty * 4 + 3) * 64 + j];
            const float* vrow = &v_s[j * 260 + tx];
#pragma unroll
            for (int j2 = 0; j2 < 16; j2++) {
                const float vv = vrow[16 * j2];
                acc[0][j2] += pa0 * vv;
                acc[1][j2] += pa1 * vv;
                acc[2][j2] += pa2 * vv;
                acc[3][j2] += pa3 * vv;
            }
        }
    }

    // epilogue: out[b,c,n] = gamma * acc/(l * sqrt(N)) + x[b,c,n]
    const float g = gamma[0];
#pragma unroll
    for (int i = 0; i < 4; i++) {
        const float inv = 1.0f / (l_i[i] * 64.0f);   // sqrt(4096) = 64
        const int n = n0 + ty * 4 + i;
#pragma unroll
        for (int j2 = 0; j2 < 16; j2++) {
            const int c = tx + 16 * j2;
            const size_t gi = ((size_t)b * CH + c) * NPOS + n;
            out[gi] = g * acc[i][j2] * inv + x[gi];
        }
    }
}

// ---------------------------------------------------------------------------
extern "C" void kernel_launch(void* const* d_in, const int* in_sizes, int n_in,
                              void* d_out, int out_size)
{
    const float* x     = (const float*)d_in[0];
    const float* Wq    = (const float*)d_in[1];
    const float* bq    = (const float*)d_in[2];
    const float* Wk    = (const float*)d_in[3];
    const float* bk    = (const float*)d_in[4];
    const float* Wv    = (const float*)d_in[5];
    const float* bv    = (const float*)d_in[6];
    const float* gamma = (const float*)d_in[7];
    float* out = (float*)d_out;

    const int qkv_smem  = 4 * 64 * 68 * (int)sizeof(float);                 // 69632 B
    const int attn_smem = (3 * 64 * 260 + 64 * 64) * (int)sizeof(float);    // 216064 B

    cudaFuncSetAttribute(qkv_kernel,  cudaFuncAttributeMaxDynamicSharedMemorySize, qkv_smem);
    cudaFuncSetAttribute(attn_kernel, cudaFuncAttributeMaxDynamicSharedMemorySize, attn_smem);

    qkv_kernel<<<dim3(NPOS / 64, CH / 64, BATCH), 256, qkv_smem>>>(x, Wq, bq, Wk, bk, Wv, bv);
    attn_kernel<<<dim3(NPOS / 64, BATCH), 256, attn_smem>>>(x, gamma, out);
}

// round 6
// speedup vs baseline: 6.0119x; 6.0119x over previous
#include <cuda_runtime.h>
#include <cuda_bf16.h>
#include <cstdint>

#define NPOS 4096
#define CH   256
#define BATCH 8
#define QT   128          // queries per CTA
#define KTILE 64          // keys per tile
#define NKT  (NPOS / KTILE)

// bf16 scratch written by qkv_kernel, all in (b, n, c) layout, c contiguous
__device__ __align__(16) __nv_bfloat16 g_q[BATCH * NPOS * CH];
__device__ __align__(16) __nv_bfloat16 g_k[BATCH * NPOS * CH];
__device__ __align__(16) __nv_bfloat16 g_v[BATCH * NPOS * CH];

// ---------------------------------------------------------------------------
// helpers
// ---------------------------------------------------------------------------
__device__ __forceinline__ uint32_t s2u(const void* p) {
    uint32_t a;
    asm("{ .reg .u64 t; cvta.to.shared.u64 t, %1; cvt.u32.u64 %0, t; }" : "=r"(a) : "l"(p));
    return a;
}
__device__ __forceinline__ void cpa16(uint32_t s, const void* g) {
    asm volatile("cp.async.cg.shared.global [%0], [%1], 16;" :: "r"(s), "l"(g));
}
__device__ __forceinline__ void cp_commit() { asm volatile("cp.async.commit_group;"); }
template <int N> __device__ __forceinline__ void cp_wait() {
    asm volatile("cp.async.wait_group %0;" :: "n"(N));
}
__device__ __forceinline__ void ldsm4(uint32_t* r, uint32_t a) {
    asm volatile("ldmatrix.sync.aligned.m8n8.x4.shared.b16 {%0,%1,%2,%3}, [%4];"
        : "=r"(r[0]), "=r"(r[1]), "=r"(r[2]), "=r"(r[3]) : "r"(a));
}
__device__ __forceinline__ void ldsm4t(uint32_t* r, uint32_t a) {
    asm volatile("ldmatrix.sync.aligned.m8n8.x4.trans.shared.b16 {%0,%1,%2,%3}, [%4];"
        : "=r"(r[0]), "=r"(r[1]), "=r"(r[2]), "=r"(r[3]) : "r"(a));
}
__device__ __forceinline__ void mma16816(float* d, const uint32_t* a, uint32_t b0, uint32_t b1) {
    asm volatile("mma.sync.aligned.m16n8k16.row.col.f32.bf16.bf16.f32 "
        "{%0,%1,%2,%3}, {%4,%5,%6,%7}, {%8,%9}, {%0,%1,%2,%3};"
        : "+f"(d[0]), "+f"(d[1]), "+f"(d[2]), "+f"(d[3])
        : "r"(a[0]), "r"(a[1]), "r"(a[2]), "r"(a[3]), "r"(b0), "r"(b1));
}
__device__ __forceinline__ float ex2(float x) {
    float r;
    asm("ex2.approx.f32 %0, %1;" : "=f"(r) : "f"(x));
    return r;
}
#define L2E 1.4426950408889634f

// ---------------------------------------------------------------------------
// Kernel 1: fused QKV projection (SIMT fp32 math, bf16 stores)
// ---------------------------------------------------------------------------
__global__ __launch_bounds__(256, 2) void qkv_kernel(
    const float* __restrict__ x,
    const float* __restrict__ Wq, const float* __restrict__ bq,
    const float* __restrict__ Wk, const float* __restrict__ bk,
    const float* __restrict__ Wv, const float* __restrict__ bv)
{
    extern __shared__ float sm[];
    float* xs  = sm;
    float* wqs = xs  + 64 * 68;
    float* wks = wqs + 64 * 68;
    float* wvs = wks + 64 * 68;

    const int tid = threadIdx.x;
    const int tx = tid & 15, ty = tid >> 4;
    const int ntile = blockIdx.x * 64;
    const int otile = blockIdx.y * 64;
    const int b = blockIdx.z;

    float aq[4][4], ak[4][4], av[4][4];
#pragma unroll
    for (int j = 0; j < 4; j++) {
        const int o = otile + tx + 16 * j;
        const float vbq = bq[o], vbk = bk[o], vbv = bv[o];
#pragma unroll
        for (int i = 0; i < 4; i++) { aq[i][j] = vbq; ak[i][j] = vbk; av[i][j] = vbv; }
    }

    for (int cc = 0; cc < CH / 64; cc++) {
        __syncthreads();
#pragma unroll
        for (int it = 0; it < 4; it++) {
            const int lin = tid + it * 256;
            const int c_l = lin >> 4;
            const int n0  = (lin & 15) * 4;
            const float4 t = *(const float4*)&x[((size_t)(b * CH + cc * 64 + c_l)) * NPOS + ntile + n0];
            xs[(n0 + 0) * 68 + c_l] = t.x;
            xs[(n0 + 1) * 68 + c_l] = t.y;
            xs[(n0 + 2) * 68 + c_l] = t.z;
            xs[(n0 + 3) * 68 + c_l] = t.w;
        }
#pragma unroll
        for (int it = 0; it < 4; it++) {
            const int lin = tid + it * 256;
            const int o_l = lin >> 4;
            const int c4  = (lin & 15) * 4;
            const size_t gofs = (size_t)(otile + o_l) * CH + cc * 64 + c4;
            *(float4*)&wqs[o_l * 68 + c4] = *(const float4*)&Wq[gofs];
            *(float4*)&wks[o_l * 68 + c4] = *(const float4*)&Wk[gofs];
            *(float4*)&wvs[o_l * 68 + c4] = *(const float4*)&Wv[gofs];
        }
        __syncthreads();

#pragma unroll 4
        for (int c0 = 0; c0 < 64; c0 += 4) {
            float4 a4[4];
#pragma unroll
            for (int i = 0; i < 4; i++)
                a4[i] = *(const float4*)&xs[(ty * 4 + i) * 68 + c0];
#pragma unroll
            for (int j = 0; j < 4; j++) {
                const int orow = (tx + 16 * j) * 68 + c0;
                float4 w4;
                w4 = *(const float4*)&wqs[orow];
#pragma unroll
                for (int i = 0; i < 4; i++)
                    aq[i][j] += a4[i].x * w4.x + a4[i].y * w4.y + a4[i].z * w4.z + a4[i].w * w4.w;
                w4 = *(const float4*)&wks[orow];
#pragma unroll
                for (int i = 0; i < 4; i++)
                    ak[i][j] += a4[i].x * w4.x + a4[i].y * w4.y + a4[i].z * w4.z + a4[i].w * w4.w;
                w4 = *(const float4*)&wvs[orow];
#pragma unroll
                for (int i = 0; i < 4; i++)
                    av[i][j] += a4[i].x * w4.x + a4[i].y * w4.y + a4[i].z * w4.z + a4[i].w * w4.w;
            }
        }
    }

#pragma unroll
    for (int i = 0; i < 4; i++) {
        const int n = ntile + ty * 4 + i;
#pragma unroll
        for (int j = 0; j < 4; j++) {
            const int o = otile + tx + 16 * j;
            const size_t gi = ((size_t)b * NPOS + n) * CH + o;
            g_q[gi] = __float2bfloat16(aq[i][j]);
            g_k[gi] = __float2bfloat16(ak[i][j]);
            g_v[gi] = __float2bfloat16(av[i][j]);
        }
    }
}

// ---------------------------------------------------------------------------
// Kernel 2: HMMA (mma.sync) flash attention.
// Grid (32, 8), block 256 (8 warps, 16 query rows each).
// Smem rows padded to 528 B (33 x 16B) -> conflict-free ldmatrix.
//   Q:  128 x 528 = 67584
//   K:  2 x 64 x 528 = 67584
//   V:  2 x 64 x 528 = 67584      total 202752 B
// ---------------------------------------------------------------------------
#define RS   528u
#define QO   0u
#define KO   67584u
#define VO   135168u
#define KVB  33792u
#define ATTN_SMEM 202752u

__global__ __launch_bounds__(256, 1) void attn_kernel(
    const float* __restrict__ x,
    const float* __restrict__ gamma,
    float* __restrict__ out)
{
    extern __shared__ __align__(16) char smem[];
    const uint32_t sb = s2u(smem);
    const int tid = threadIdx.x;
    const int lane = tid & 31, wid = tid >> 5;
    const int n0 = blockIdx.x * QT;
    const int b  = blockIdx.y;

    const char* qg = (const char*)(g_q + ((size_t)b * NPOS + n0) * CH);
    const char* kg = (const char*)(g_k + (size_t)b * NPOS * CH);
    const char* vg = (const char*)(g_v + (size_t)b * NPOS * CH);

    // ---- preload Q + tile 0 (group 0) ----
#pragma unroll
    for (int it = 0; it < 16; it++) {
        const int g = tid + it * 256;            // 4096 granules
        const int row = g >> 5, ch = g & 31;
        cpa16(sb + QO + row * RS + ch * 16, qg + row * 512 + ch * 16);
    }
#pragma unroll
    for (int it = 0; it < 8; it++) {
        const int g = tid + it * 256;            // 2048 granules each
        const int row = g >> 5, ch = g & 31;
        cpa16(sb + KO + row * RS + ch * 16, kg + row * 512 + ch * 16);
        cpa16(sb + VO + row * RS + ch * 16, vg + row * 512 + ch * 16);
    }
    cp_commit();

    // per-thread ldmatrix base addresses (lane-dependent part)
    const uint32_t lrow = (lane & 15);
    const uint32_t lcol = (lane >> 4) << 4;      // bytes
    const uint32_t aB = sb + QO + (wid * 16 + lrow) * RS + lcol;
    const uint32_t kB = sb + KO + lrow * RS + lcol;
    const uint32_t vB = sb + VO + lrow * RS + lcol;

    float o[32][4];
#pragma unroll
    for (int t = 0; t < 32; t++)
#pragma unroll
        for (int u = 0; u < 4; u++) o[t][u] = 0.f;
    float m0 = -1e30f, m1 = -1e30f, l0 = 0.f, l1 = 0.f;

    for (int kt = 0; kt < NKT; kt++) {
        const uint32_t buf = (kt & 1) * KVB;
        if (kt > 0) __syncthreads();             // close previous compute
        if (kt + 1 < NKT) {
            const uint32_t nbuf = ((kt + 1) & 1) * KVB;
            const char* kgt = kg + (size_t)(kt + 1) * KTILE * 512;
            const char* vgt = vg + (size_t)(kt + 1) * KTILE * 512;
#pragma unroll
            for (int it = 0; it < 8; it++) {
                const int g = tid + it * 256;
                const int row = g >> 5, ch = g & 31;
                cpa16(sb + KO + nbuf + row * RS + ch * 16, kgt + row * 512 + ch * 16);
                cpa16(sb + VO + nbuf + row * RS + ch * 16, vgt + row * 512 + ch * 16);
            }
            cp_commit();
            cp_wait<1>();
        } else {
            cp_wait<0>();
        }
        __syncthreads();

        // ---- S = Q K^T  (16 x 64 per warp) ----
        float s[8][4];
#pragma unroll
        for (int t = 0; t < 8; t++)
#pragma unroll
            for (int u = 0; u < 4; u++) s[t][u] = 0.f;

#pragma unroll 4
        for (int cs = 0; cs < 16; cs++) {
            uint32_t a[4];
            ldsm4(a, aB + cs * 32);
#pragma unroll
            for (int k16 = 0; k16 < 4; k16++) {
                uint32_t kr[4];
                ldsm4(kr, kB + buf + k16 * (16 * RS) + cs * 32);
                // B fragment = {k-lo, k-hi} per 8-key group:
                // keys 0-7 of this 16-key block -> {kr[0], kr[2]}, keys 8-15 -> {kr[1], kr[3]}
                mma16816(s[2 * k16 + 0], a, kr[0], kr[2]);
                mma16816(s[2 * k16 + 1], a, kr[1], kr[3]);
            }
        }

        // ---- online softmax ----
        float mt0 = s[0][0], mt1 = s[0][2];
#pragma unroll
        for (int t = 0; t < 8; t++) {
            mt0 = fmaxf(mt0, fmaxf(s[t][0], s[t][1]));
            mt1 = fmaxf(mt1, fmaxf(s[t][2], s[t][3]));
        }
        mt0 = fmaxf(mt0, __shfl_xor_sync(~0u, mt0, 1));
        mt0 = fmaxf(mt0, __shfl_xor_sync(~0u, mt0, 2));
        mt1 = fmaxf(mt1, __shfl_xor_sync(~0u, mt1, 1));
        mt1 = fmaxf(mt1, __shfl_xor_sync(~0u, mt1, 2));

        const float mn0 = fmaxf(m0, mt0), mn1 = fmaxf(m1, mt1);
        if (mn0 > m0 || mn1 > m1) {
            const float sc0 = ex2((m0 - mn0) * L2E);
            const float sc1 = ex2((m1 - mn1) * L2E);
            l0 *= sc0; l1 *= sc1;
#pragma unroll
            for (int t = 0; t < 32; t++) {
                o[t][0] *= sc0; o[t][1] *= sc0;
                o[t][2] *= sc1; o[t][3] *= sc1;
            }
            m0 = mn0; m1 = mn1;
        }
        const float mL0 = m0 * L2E, mL1 = m1 * L2E;
        float ps0 = 0.f, ps1 = 0.f;
#pragma unroll
        for (int t = 0; t < 8; t++) {
            s[t][0] = ex2(fmaf(s[t][0], L2E, -mL0));
            s[t][1] = ex2(fmaf(s[t][1], L2E, -mL0));
            s[t][2] = ex2(fmaf(s[t][2], L2E, -mL1));
            s[t][3] = ex2(fmaf(s[t][3], L2E, -mL1));
            ps0 += s[t][0] + s[t][1];
            ps1 += s[t][2] + s[t][3];
        }
        l0 += ps0; l1 += ps1;

        // ---- O += P V ----
#pragma unroll
        for (int js = 0; js < 4; js++) {
            uint32_t pa[4];
            {
                const __nv_bfloat162 h0 = __floats2bfloat162_rn(s[2 * js][0], s[2 * js][1]);
                const __nv_bfloat162 h1 = __floats2bfloat162_rn(s[2 * js][2], s[2 * js][3]);
                const __nv_bfloat162 h2 = __floats2bfloat162_rn(s[2 * js + 1][0], s[2 * js + 1][1]);
                const __nv_bfloat162 h3 = __floats2bfloat162_rn(s[2 * js + 1][2], s[2 * js + 1][3]);
                pa[0] = *(const uint32_t*)&h0;
                pa[1] = *(const uint32_t*)&h1;
                pa[2] = *(const uint32_t*)&h2;
                pa[3] = *(const uint32_t*)&h3;
            }
#pragma unroll
            for (int cp = 0; cp < 16; cp++) {
                uint32_t vr[4];
                ldsm4t(vr, vB + buf + js * (16 * RS) + cp * 32);
                mma16816(o[2 * cp + 0], pa, vr[0], vr[1]);
                mma16816(o[2 * cp + 1], pa, vr[2], vr[3]);
            }
        }
    }

    // ---- epilogue ----
    l0 += __shfl_xor_sync(~0u, l0, 1);
    l0 += __shfl_xor_sync(~0u, l0, 2);
    l1 += __shfl_xor_sync(~0u, l1, 1);
    l1 += __shfl_xor_sync(~0u, l1, 2);
    const float g0 = gamma[0];
    const float e0 = g0 / (l0 * 64.0f);          // sqrt(4096) = 64
    const float e1 = g0 / (l1 * 64.0f);
    const int nrow = n0 + wid * 16 + (lane >> 2);
#pragma unroll
    for (int t = 0; t < 32; t++) {
        const int c = t * 8 + 2 * (lane & 3);
        const size_t i0 = ((size_t)b * CH + c) * NPOS + nrow;
        out[i0]            = o[t][0] * e0 + x[i0];
        out[i0 + NPOS]     = o[t][1] * e0 + x[i0 + NPOS];
        out[i0 + 8]        = o[t][2] * e1 + x[i0 + 8];
        out[i0 + NPOS + 8] = o[t][3] * e1 + x[i0 + NPOS + 8];
    }
}

// ---------------------------------------------------------------------------
extern "C" void kernel_launch(void* const* d_in, const int* in_sizes, int n_in,
                              void* d_out, int out_size)
{
    const float* x     = (const float*)d_in[0];
    const float* Wq    = (const float*)d_in[1];
    const float* bq    = (const float*)d_in[2];
    const float* Wk    = (const float*)d_in[3];
    const float* bk    = (const float*)d_in[4];
    const float* Wv    = (const float*)d_in[5];
    const float* bv    = (const float*)d_in[6];
    const float* gamma = (const float*)d_in[7];
    float* out = (float*)d_out;

    const int qkv_smem = 4 * 64 * 68 * (int)sizeof(float);

    cudaFuncSetAttribute(qkv_kernel,  cudaFuncAttributeMaxDynamicSharedMemorySize, qkv_smem);
    cudaFuncSetAttribute(attn_kernel, cudaFuncAttributeMaxDynamicSharedMemorySize, ATTN_SMEM);

    qkv_kernel<<<dim3(NPOS / 64, CH / 64, BATCH), 256, qkv_smem>>>(x, Wq, bq, Wk, bk, Wv, bv);
    attn_kernel<<<dim3(NPOS / QT, BATCH), 256, ATTN_SMEM>>>(x, gamma, out);
}

// round 9
// speedup vs baseline: 7.5094x; 1.2491x over previous
#include <cuda_runtime.h>
#include <cuda_bf16.h>
#include <cstdint>

#define NPOS 4096
#define CH   256
#define BATCH 8
#define QT   128          // queries per CTA
#define KTILE 64          // keys per tile
#define NKT  (NPOS / KTILE)

// bf16 scratch, all in (b, n, c) layout, c contiguous
__device__ __align__(16) __nv_bfloat16 g_q[BATCH * NPOS * CH];
__device__ __align__(16) __nv_bfloat16 g_k[BATCH * NPOS * CH];
__device__ __align__(16) __nv_bfloat16 g_v[BATCH * NPOS * CH];

// ---------------------------------------------------------------------------
// helpers
// ---------------------------------------------------------------------------
__device__ __forceinline__ uint32_t s2u(const void* p) {
    uint32_t a;
    asm("{ .reg .u64 t; cvta.to.shared.u64 t, %1; cvt.u32.u64 %0, t; }" : "=r"(a) : "l"(p));
    return a;
}
__device__ __forceinline__ void cpa16(uint32_t s, const void* g) {
    asm volatile("cp.async.cg.shared.global [%0], [%1], 16;" :: "r"(s), "l"(g));
}
__device__ __forceinline__ void cp_commit() { asm volatile("cp.async.commit_group;"); }
template <int N> __device__ __forceinline__ void cp_wait() {
    asm volatile("cp.async.wait_group %0;" :: "n"(N));
}
__device__ __forceinline__ void ldsm4(uint32_t* r, uint32_t a) {
    asm volatile("ldmatrix.sync.aligned.m8n8.x4.shared.b16 {%0,%1,%2,%3}, [%4];"
        : "=r"(r[0]), "=r"(r[1]), "=r"(r[2]), "=r"(r[3]) : "r"(a));
}
__device__ __forceinline__ void ldsm4t(uint32_t* r, uint32_t a) {
    asm volatile("ldmatrix.sync.aligned.m8n8.x4.trans.shared.b16 {%0,%1,%2,%3}, [%4];"
        : "=r"(r[0]), "=r"(r[1]), "=r"(r[2]), "=r"(r[3]) : "r"(a));
}
__device__ __forceinline__ void mma16816(float* d, const uint32_t* a, uint32_t b0, uint32_t b1) {
    asm volatile("mma.sync.aligned.m16n8k16.row.col.f32.bf16.bf16.f32 "
        "{%0,%1,%2,%3}, {%4,%5,%6,%7}, {%8,%9}, {%0,%1,%2,%3};"
        : "+f"(d[0]), "+f"(d[1]), "+f"(d[2]), "+f"(d[3])
        : "r"(a[0]), "r"(a[1]), "r"(a[2]), "r"(a[3]), "r"(b0), "r"(b1));
}
__device__ __forceinline__ float ex2(float x) {
    float r;
    asm("ex2.approx.f32 %0, %1;" : "=f"(r) : "f"(x));
    return r;
}
#define L2E 1.4426950408889634f

// ---------------------------------------------------------------------------
// Kernel 1: QKV projection on HMMA.
// Grid (32, 8), 256 threads (8 warps). Per CTA: 128 positions x 256 outputs,
// 3 phases (q, k, v) sharing one x tile.
//   xs: x tile, (c, n) bf16, 256 rows x 272 B  = 69632
//   ws: W tile, (o, c) bf16, 256 rows x 528 B  = 135168
//   bias: 256 fp32                             = 1024
// D[n, o]: A = x^T via ldmatrix.trans on xs, B = W via ldmatrix on ws.
// ---------------------------------------------------------------------------
#define XSTR 272u
#define WOFF 69632u
#define WSTR 528u
#define BOFF (WOFF + 135168u)
#define QKV_SMEM (BOFF + 1024u)

__global__ __launch_bounds__(256, 1) void qkv_mma_kernel(
    const float* __restrict__ x,
    const float* __restrict__ Wq, const float* __restrict__ bq,
    const float* __restrict__ Wk, const float* __restrict__ bk,
    const float* __restrict__ Wv, const float* __restrict__ bv)
{
    extern __shared__ __align__(16) char smem[];
    const uint32_t sb = s2u(smem);
    const int tid = threadIdx.x;
    const int lane = tid & 31, wid = tid >> 5;
    const int ntile = blockIdx.x * QT;
    const int b = blockIdx.y;

    // ---- x tile: (b,c,n) fp32 gmem -> (c, n) bf16 smem ----
#pragma unroll
    for (int it = 0; it < 32; it++) {
        const int lin = tid + it * 256;          // 8192 float4s
        const int c = lin >> 5;
        const int n4 = (lin & 31) * 4;
        const float4 t = *(const float4*)&x[((size_t)(b * CH + c)) * NPOS + ntile + n4];
        const __nv_bfloat162 h0 = __floats2bfloat162_rn(t.x, t.y);
        const __nv_bfloat162 h1 = __floats2bfloat162_rn(t.z, t.w);
        uint2 pk;
        pk.x = *(const uint32_t*)&h0;
        pk.y = *(const uint32_t*)&h1;
        *(uint2*)(smem + c * XSTR + n4 * 2) = pk;
    }

    const float* Ws[3] = {Wq, Wk, Wv};
    const float* Bs[3] = {bq, bk, bv};
    __nv_bfloat16* const obase = (__nv_bfloat16*)0;  // placeholder
    (void)obase;
    __nv_bfloat16* Os[3] = {
        g_q + ((size_t)b * NPOS + ntile) * CH,
        g_k + ((size_t)b * NPOS + ntile) * CH,
        g_v + ((size_t)b * NPOS + ntile) * CH };

    // A fragment address (ldmatrix.trans on xs):
    //   lanes 0-7:  c rows 0-7,  n bytes +0   -> a0 = (n0-7,  c0-7)
    //   lanes 8-15: c rows 0-7,  n bytes +16  -> a1 = (n8-15, c0-7)
    //   lanes 16-23:c rows 8-15, n bytes +0   -> a2 = (n0-7,  c8-15)
    //   lanes 24-31:c rows 8-15, n bytes +16  -> a3 = (n8-15, c8-15)
    const uint32_t aRow = (lane & 7) + ((lane >> 4) & 1) * 8;
    const uint32_t aColB = wid * 32 + ((lane >> 3) & 1) * 16;
    const uint32_t aB = sb + aRow * XSTR + aColB;
    // B fragment address (ldmatrix non-trans on ws) — attn-K pattern
    const uint32_t wB = sb + WOFF + (lane & 15) * WSTR + (lane >> 4) * 16;

    float* bias_s = (float*)(smem + BOFF);

    for (int m = 0; m < 3; m++) {
        // ---- load W_m: (o,c) fp32 -> (o, c) bf16 smem; bias -> smem ----
        const float* W = Ws[m];
#pragma unroll
        for (int it = 0; it < 64; it++) {
            const int lin = tid + it * 256;      // 16384 float4s
            const int o = lin >> 6;
            const int c4 = (lin & 63) * 4;
            const float4 t = *(const float4*)&W[(size_t)o * CH + c4];
            const __nv_bfloat162 h0 = __floats2bfloat162_rn(t.x, t.y);
            const __nv_bfloat162 h1 = __floats2bfloat162_rn(t.z, t.w);
            uint2 pk;
            pk.x = *(const uint32_t*)&h0;
            pk.y = *(const uint32_t*)&h1;
            *(uint2*)(smem + WOFF + o * WSTR + c4 * 2) = pk;
        }
        bias_s[tid] = Bs[m][tid];
        __syncthreads();

        // ---- compute D[n, o] : 16 n-rows per warp x 256 o ----
        float s[32][4];
#pragma unroll
        for (int t = 0; t < 32; t++)
#pragma unroll
            for (int u = 0; u < 4; u++) s[t][u] = 0.f;

#pragma unroll 2
        for (int cs = 0; cs < 16; cs++) {
            uint32_t a[4];
            ldsm4t(a, aB + cs * (16 * XSTR));
#pragma unroll
            for (int ot = 0; ot < 16; ot++) {
                uint32_t w[4];
                ldsm4(w, wB + ot * (16 * WSTR) + cs * 32);
                mma16816(s[2 * ot + 0], a, w[0], w[2]);
                mma16816(s[2 * ot + 1], a, w[1], w[3]);
            }
        }

        // ---- epilogue: +bias, bf16, store to (b, n, c) scratch ----
        __nv_bfloat16* outp = Os[m];
        const int r0 = wid * 16 + (lane >> 2);
#pragma unroll
        for (int t = 0; t < 32; t++) {
            const int o0 = t * 8 + 2 * (lane & 3);
            const float b0 = bias_s[o0], b1 = bias_s[o0 + 1];
            const __nv_bfloat162 lo = __floats2bfloat162_rn(s[t][0] + b0, s[t][1] + b1);
            const __nv_bfloat162 hi = __floats2bfloat162_rn(s[t][2] + b0, s[t][3] + b1);
            *(uint32_t*)&outp[(size_t)r0 * CH + o0]       = *(const uint32_t*)&lo;
            *(uint32_t*)&outp[(size_t)(r0 + 8) * CH + o0] = *(const uint32_t*)&hi;
        }
        __syncthreads();   // protect ws/bias before next phase overwrites
    }
}

// ---------------------------------------------------------------------------
// Kernel 2: HMMA flash attention (unchanged from R6).
// ---------------------------------------------------------------------------
#define RS   528u
#define QO   0u
#define KO   67584u
#define VO   135168u
#define KVB  33792u
#define ATTN_SMEM 202752u

__global__ __launch_bounds__(256, 1) void attn_kernel(
    const float* __restrict__ x,
    const float* __restrict__ gamma,
    float* __restrict__ out)
{
    extern __shared__ __align__(16) char smem[];
    const uint32_t sb = s2u(smem);
    const int tid = threadIdx.x;
    const int lane = tid & 31, wid = tid >> 5;
    const int n0 = blockIdx.x * QT;
    const int b  = blockIdx.y;

    const char* qg = (const char*)(g_q + ((size_t)b * NPOS + n0) * CH);
    const char* kg = (const char*)(g_k + (size_t)b * NPOS * CH);
    const char* vg = (const char*)(g_v + (size_t)b * NPOS * CH);

#pragma unroll
    for (int it = 0; it < 16; it++) {
        const int g = tid + it * 256;
        const int row = g >> 5, ch = g & 31;
        cpa16(sb + QO + row * RS + ch * 16, qg + row * 512 + ch * 16);
    }
#pragma unroll
    for (int it = 0; it < 8; it++) {
        const int g = tid + it * 256;
        const int row = g >> 5, ch = g & 31;
        cpa16(sb + KO + row * RS + ch * 16, kg + row * 512 + ch * 16);
        cpa16(sb + VO + row * RS + ch * 16, vg + row * 512 + ch * 16);
    }
    cp_commit();

    const uint32_t lrow = (lane & 15);
    const uint32_t lcol = (lane >> 4) << 4;
    const uint32_t aB = sb + QO + (wid * 16 + lrow) * RS + lcol;
    const uint32_t kB = sb + KO + lrow * RS + lcol;
    const uint32_t vB = sb + VO + lrow * RS + lcol;

    float o[32][4];
#pragma unroll
    for (int t = 0; t < 32; t++)
#pragma unroll
        for (int u = 0; u < 4; u++) o[t][u] = 0.f;
    float m0 = -1e30f, m1 = -1e30f, l0 = 0.f, l1 = 0.f;

    for (int kt = 0; kt < NKT; kt++) {
        const uint32_t buf = (kt & 1) * KVB;
        if (kt > 0) __syncthreads();
        if (kt + 1 < NKT) {
            const uint32_t nbuf = ((kt + 1) & 1) * KVB;
            const char* kgt = kg + (size_t)(kt + 1) * KTILE * 512;
            const char* vgt = vg + (size_t)(kt + 1) * KTILE * 512;
#pragma unroll
            for (int it = 0; it < 8; it++) {
                const int g = tid + it * 256;
                const int row = g >> 5, ch = g & 31;
                cpa16(sb + KO + nbuf + row * RS + ch * 16, kgt + row * 512 + ch * 16);
                cpa16(sb + VO + nbuf + row * RS + ch * 16, vgt + row * 512 + ch * 16);
            }
            cp_commit();
            cp_wait<1>();
        } else {
            cp_wait<0>();
        }
        __syncthreads();

        float s[8][4];
#pragma unroll
        for (int t = 0; t < 8; t++)
#pragma unroll
            for (int u = 0; u < 4; u++) s[t][u] = 0.f;

#pragma unroll 4
        for (int cs = 0; cs < 16; cs++) {
            uint32_t a[4];
            ldsm4(a, aB + cs * 32);
#pragma unroll
            for (int k16 = 0; k16 < 4; k16++) {
                uint32_t kr[4];
                ldsm4(kr, kB + buf + k16 * (16 * RS) + cs * 32);
                mma16816(s[2 * k16 + 0], a, kr[0], kr[2]);
                mma16816(s[2 * k16 + 1], a, kr[1], kr[3]);
            }
        }

        float mt0 = s[0][0], mt1 = s[0][2];
#pragma unroll
        for (int t = 0; t < 8; t++) {
            mt0 = fmaxf(mt0, fmaxf(s[t][0], s[t][1]));
            mt1 = fmaxf(mt1, fmaxf(s[t][2], s[t][3]));
        }
        mt0 = fmaxf(mt0, __shfl_xor_sync(~0u, mt0, 1));
        mt0 = fmaxf(mt0, __shfl_xor_sync(~0u, mt0, 2));
        mt1 = fmaxf(mt1, __shfl_xor_sync(~0u, mt1, 1));
        mt1 = fmaxf(mt1, __shfl_xor_sync(~0u, mt1, 2));

        const float mn0 = fmaxf(m0, mt0), mn1 = fmaxf(m1, mt1);
        if (mn0 > m0 || mn1 > m1) {
            const float sc0 = ex2((m0 - mn0) * L2E);
            const float sc1 = ex2((m1 - mn1) * L2E);
            l0 *= sc0; l1 *= sc1;
#pragma unroll
            for (int t = 0; t < 32; t++) {
                o[t][0] *= sc0; o[t][1] *= sc0;
                o[t][2] *= sc1; o[t][3] *= sc1;
            }
            m0 = mn0; m1 = mn1;
        }
        const float mL0 = m0 * L2E, mL1 = m1 * L2E;
        float ps0 = 0.f, ps1 = 0.f;
#pragma unroll
        for (int t = 0; t < 8; t++) {
            s[t][0] = ex2(fmaf(s[t][0], L2E, -mL0));
            s[t][1] = ex2(fmaf(s[t][1], L2E, -mL0));
            s[t][2] = ex2(fmaf(s[t][2], L2E, -mL1));
            s[t][3] = ex2(fmaf(s[t][3], L2E, -mL1));
            ps0 += s[t][0] + s[t][1];
            ps1 += s[t][2] + s[t][3];
        }
        l0 += ps0; l1 += ps1;

#pragma unroll
        for (int js = 0; js < 4; js++) {
            uint32_t pa[4];
            {
                const __nv_bfloat162 h0 = __floats2bfloat162_rn(s[2 * js][0], s[2 * js][1]);
                const __nv_bfloat162 h1 = __floats2bfloat162_rn(s[2 * js][2], s[2 * js][3]);
                const __nv_bfloat162 h2 = __floats2bfloat162_rn(s[2 * js + 1][0], s[2 * js + 1][1]);
                const __nv_bfloat162 h3 = __floats2bfloat162_rn(s[2 * js + 1][2], s[2 * js + 1][3]);
                pa[0] = *(const uint32_t*)&h0;
                pa[1] = *(const uint32_t*)&h1;
                pa[2] = *(const uint32_t*)&h2;
                pa[3] = *(const uint32_t*)&h3;
            }
#pragma unroll
            for (int cp = 0; cp < 16; cp++) {
                uint32_t vr[4];
                ldsm4t(vr, vB + buf + js * (16 * RS) + cp * 32);
                mma16816(o[2 * cp + 0], pa, vr[0], vr[1]);
                mma16816(o[2 * cp + 1], pa, vr[2], vr[3]);
            }
        }
    }

    l0 += __shfl_xor_sync(~0u, l0, 1);
    l0 += __shfl_xor_sync(~0u, l0, 2);
    l1 += __shfl_xor_sync(~0u, l1, 1);
    l1 += __shfl_xor_sync(~0u, l1, 2);
    const float g0 = gamma[0];
    const float e0 = g0 / (l0 * 64.0f);
    const float e1 = g0 / (l1 * 64.0f);
    const int nrow = n0 + wid * 16 + (lane >> 2);
#pragma unroll
    for (int t = 0; t < 32; t++) {
        const int c = t * 8 + 2 * (lane & 3);
        const size_t i0 = ((size_t)b * CH + c) * NPOS + nrow;
        out[i0]            = o[t][0] * e0 + x[i0];
        out[i0 + NPOS]     = o[t][1] * e0 + x[i0 + NPOS];
        out[i0 + 8]        = o[t][2] * e1 + x[i0 + 8];
        out[i0 + NPOS + 8] = o[t][3] * e1 + x[i0 + NPOS + 8];
    }
}

// ---------------------------------------------------------------------------
extern "C" void kernel_launch(void* const* d_in, const int* in_sizes, int n_in,
                              void* d_out, int out_size)
{
    const float* x     = (const float*)d_in[0];
    const float* Wq    = (const float*)d_in[1];
    const float* bq    = (const float*)d_in[2];
    const float* Wk    = (const float*)d_in[3];
    const float* bk    = (const float*)d_in[4];
    const float* Wv    = (const float*)d_in[5];
    const float* bv    = (const float*)d_in[6];
    const float* gamma = (const float*)d_in[7];
    float* out = (float*)d_out;

    cudaFuncSetAttribute(qkv_mma_kernel, cudaFuncAttributeMaxDynamicSharedMemorySize, QKV_SMEM);
    cudaFuncSetAttribute(attn_kernel,    cudaFuncAttributeMaxDynamicSharedMemorySize, ATTN_SMEM);

    qkv_mma_kernel<<<dim3(NPOS / QT, BATCH), 256, QKV_SMEM>>>(x, Wq, bq, Wk, bk, Wv, bv);
    attn_kernel<<<dim3(NPOS / QT, BATCH), 256, ATTN_SMEM>>>(x, gamma, out);
}

// round 10
// speedup vs baseline: 8.8111x; 1.1733x over previous
#include <cuda_runtime.h>
#include <cuda_bf16.h>
#include <cuda_fp16.h>
#include <cstdint>

#define NPOS 4096
#define CH   256
#define BATCH 8
#define QT   128          // queries per CTA (attn)
#define KTILE 64          // keys per tile
#define NKT  (NPOS / KTILE)

// scratch
__device__ __align__(16) __nv_bfloat16 g_xb[BATCH * CH * NPOS];  // x bf16 (b,c,n)
__device__ __align__(16) __nv_bfloat16 g_wb[3 * CH * CH];        // W bf16 (m,o,c)
__device__ __align__(16) __nv_bfloat16 g_q[BATCH * NPOS * CH];   // (b,n,c)
__device__ __align__(16) __nv_bfloat16 g_k[BATCH * NPOS * CH];   // (b,n,c)
__device__ __align__(16) __half       g_v[BATCH * NPOS * CH];    // (b,n,c)  f16!

// ---------------------------------------------------------------------------
// helpers
// ---------------------------------------------------------------------------
__device__ __forceinline__ uint32_t s2u(const void* p) {
    uint32_t a;
    asm("{ .reg .u64 t; cvta.to.shared.u64 t, %1; cvt.u32.u64 %0, t; }" : "=r"(a) : "l"(p));
    return a;
}
__device__ __forceinline__ void cpa16(uint32_t s, const void* g) {
    asm volatile("cp.async.cg.shared.global [%0], [%1], 16;" :: "r"(s), "l"(g));
}
__device__ __forceinline__ void cp_commit() { asm volatile("cp.async.commit_group;"); }
template <int N> __device__ __forceinline__ void cp_wait() {
    asm volatile("cp.async.wait_group %0;" :: "n"(N));
}
__device__ __forceinline__ void ldsm4(uint32_t* r, uint32_t a) {
    asm volatile("ldmatrix.sync.aligned.m8n8.x4.shared.b16 {%0,%1,%2,%3}, [%4];"
        : "=r"(r[0]), "=r"(r[1]), "=r"(r[2]), "=r"(r[3]) : "r"(a));
}
__device__ __forceinline__ void ldsm4t(uint32_t* r, uint32_t a) {
    asm volatile("ldmatrix.sync.aligned.m8n8.x4.trans.shared.b16 {%0,%1,%2,%3}, [%4];"
        : "=r"(r[0]), "=r"(r[1]), "=r"(r[2]), "=r"(r[3]) : "r"(a));
}
__device__ __forceinline__ void mma16816(float* d, const uint32_t* a, uint32_t b0, uint32_t b1) {
    asm volatile("mma.sync.aligned.m16n8k16.row.col.f32.bf16.bf16.f32 "
        "{%0,%1,%2,%3}, {%4,%5,%6,%7}, {%8,%9}, {%0,%1,%2,%3};"
        : "+f"(d[0]), "+f"(d[1]), "+f"(d[2]), "+f"(d[3])
        : "r"(a[0]), "r"(a[1]), "r"(a[2]), "r"(a[3]), "r"(b0), "r"(b1));
}
__device__ __forceinline__ void mma16816h(uint32_t* d, const uint32_t* a, uint32_t b0, uint32_t b1) {
    asm volatile("mma.sync.aligned.m16n8k16.row.col.f16.f16.f16.f16 "
        "{%0,%1}, {%2,%3,%4,%5}, {%6,%7}, {%0,%1};"
        : "+r"(d[0]), "+r"(d[1])
        : "r"(a[0]), "r"(a[1]), "r"(a[2]), "r"(a[3]), "r"(b0), "r"(b1));
}
__device__ __forceinline__ float ex2(float x) {
    float r;
    asm("ex2.approx.f32 %0, %1;" : "=f"(r) : "f"(x));
    return r;
}
#define L2E 1.4426950408889634f

// ---------------------------------------------------------------------------
// Kernel 0: fp32 -> bf16 conversion of x and W.
// ---------------------------------------------------------------------------
__global__ __launch_bounds__(256) void convert_kernel(
    const float* __restrict__ x,
    const float* __restrict__ Wq, const float* __restrict__ Wk, const float* __restrict__ Wv)
{
    const int nt = gridDim.x * blockDim.x;
    const int id = blockIdx.x * blockDim.x + threadIdx.x;
#pragma unroll 1
    for (int i = id; i < (BATCH * CH * NPOS) / 4; i += nt) {
        const float4 t = ((const float4*)x)[i];
        const __nv_bfloat162 h0 = __floats2bfloat162_rn(t.x, t.y);
        const __nv_bfloat162 h1 = __floats2bfloat162_rn(t.z, t.w);
        uint2 p; p.x = *(const uint32_t*)&h0; p.y = *(const uint32_t*)&h1;
        *(uint2*)&g_xb[4 * i] = p;
    }
    const float* Ws[3] = {Wq, Wk, Wv};
#pragma unroll 1
    for (int m = 0; m < 3; m++) {
        const float* W = Ws[m];
#pragma unroll 1
        for (int i = id; i < (CH * CH) / 4; i += nt) {
            const float4 t = ((const float4*)W)[i];
            const __nv_bfloat162 h0 = __floats2bfloat162_rn(t.x, t.y);
            const __nv_bfloat162 h1 = __floats2bfloat162_rn(t.z, t.w);
            uint2 p; p.x = *(const uint32_t*)&h0; p.y = *(const uint32_t*)&h1;
            *(uint2*)&g_wb[m * CH * CH + 4 * i] = p;
        }
    }
}

// ---------------------------------------------------------------------------
// Kernel 1: QKV projection on HMMA, one projection per CTA (blockIdx.z).
// Grid (32, 8, 3), 256 threads. All staging via cp.async of bf16.
//   xs: x tile (c, n) bf16: 256 rows x 272 B = 69632
//   ws: W (o, c) bf16:      256 rows x 528 B = 135168
//   bias: 256 fp32 = 1024
// ---------------------------------------------------------------------------
#define XSTR 272u
#define WOFF 69632u
#define WSTR 528u
#define BOFF (WOFF + 135168u)
#define QKV_SMEM (BOFF + 1024u)

__global__ __launch_bounds__(256, 1) void qkv_mma_kernel(
    const float* __restrict__ bq, const float* __restrict__ bk, const float* __restrict__ bv)
{
    extern __shared__ __align__(16) char smem[];
    const uint32_t sb = s2u(smem);
    const int tid = threadIdx.x;
    const int lane = tid & 31, wid = tid >> 5;
    const int ntile = blockIdx.x * QT;
    const int b = blockIdx.y;
    const int m = blockIdx.z;

    // ---- stage x tile: (c, n) bf16, 128-n slice ----
    {
        const char* xb = (const char*)g_xb + ((size_t)(b * CH) * NPOS + ntile) * 2;
#pragma unroll
        for (int it = 0; it < 16; it++) {
            const int g = tid + it * 256;        // 4096 granules
            const int row = g >> 4, off = (g & 15) * 16;
            cpa16(sb + row * XSTR + off, xb + (size_t)row * (NPOS * 2) + off);
        }
    }
    // ---- stage W_m: (o, c) bf16 ----
    {
        const char* wb = (const char*)(g_wb + (size_t)m * CH * CH);
#pragma unroll
        for (int it = 0; it < 32; it++) {
            const int g = tid + it * 256;        // 8192 granules
            const int row = g >> 5, off = (g & 31) * 16;
            cpa16(sb + WOFF + row * WSTR + off, wb + (size_t)row * 512 + off);
        }
    }
    float* bias_s = (float*)(smem + BOFF);
    bias_s[tid] = (m == 0 ? bq : (m == 1 ? bk : bv))[tid];
    cp_commit();
    cp_wait<0>();
    __syncthreads();

    // A fragment (x^T via ldmatrix.trans on xs)
    const uint32_t aRow = (lane & 7) + ((lane >> 4) & 1) * 8;
    const uint32_t aColB = wid * 32 + ((lane >> 3) & 1) * 16;
    const uint32_t aB = sb + aRow * XSTR + aColB;
    // B fragment (W via ldmatrix non-trans on ws)
    const uint32_t wB = sb + WOFF + (lane & 15) * WSTR + (lane >> 4) * 16;

    float s[32][4];
#pragma unroll
    for (int t = 0; t < 32; t++)
#pragma unroll
        for (int u = 0; u < 4; u++) s[t][u] = 0.f;

#pragma unroll 2
    for (int cs = 0; cs < 16; cs++) {
        uint32_t a[4];
        ldsm4t(a, aB + cs * (16 * XSTR));
#pragma unroll
        for (int ot = 0; ot < 16; ot++) {
            uint32_t w[4];
            ldsm4(w, wB + ot * (16 * WSTR) + cs * 32);
            mma16816(s[2 * ot + 0], a, w[0], w[2]);
            mma16816(s[2 * ot + 1], a, w[1], w[3]);
        }
    }

    // ---- epilogue: +bias; q/k -> bf16, v -> f16 ----
    const int r0 = wid * 16 + (lane >> 2);
    const size_t obase = ((size_t)b * NPOS + ntile) * CH;
    if (m < 2) {
        __nv_bfloat16* outp = (m == 0 ? g_q : g_k) + obase;
#pragma unroll
        for (int t = 0; t < 32; t++) {
            const int o0 = t * 8 + 2 * (lane & 3);
            const float b0 = bias_s[o0], b1 = bias_s[o0 + 1];
            const __nv_bfloat162 lo = __floats2bfloat162_rn(s[t][0] + b0, s[t][1] + b1);
            const __nv_bfloat162 hi = __floats2bfloat162_rn(s[t][2] + b0, s[t][3] + b1);
            *(uint32_t*)&outp[(size_t)r0 * CH + o0]       = *(const uint32_t*)&lo;
            *(uint32_t*)&outp[(size_t)(r0 + 8) * CH + o0] = *(const uint32_t*)&hi;
        }
    } else {
        __half* outp = g_v + obase;
#pragma unroll
        for (int t = 0; t < 32; t++) {
            const int o0 = t * 8 + 2 * (lane & 3);
            const float b0 = bias_s[o0], b1 = bias_s[o0 + 1];
            const __half2 lo = __floats2half2_rn(s[t][0] + b0, s[t][1] + b1);
            const __half2 hi = __floats2half2_rn(s[t][2] + b0, s[t][3] + b1);
            *(uint32_t*)&outp[(size_t)r0 * CH + o0]       = *(const uint32_t*)&lo;
            *(uint32_t*)&outp[(size_t)(r0 + 8) * CH + o0] = *(const uint32_t*)&hi;
        }
    }
}

// ---------------------------------------------------------------------------
// Kernel 2: HMMA flash attention. QK: bf16 -> f32 D. PV: f16 -> f16 D (packed O).
// ---------------------------------------------------------------------------
#define RS   528u
#define QO   0u
#define KO   67584u
#define VO   135168u
#define KVB  33792u
#define ATTN_SMEM 202752u

__global__ __launch_bounds__(256, 1) void attn_kernel(
    const float* __restrict__ x,
    const float* __restrict__ gamma,
    float* __restrict__ out)
{
    extern __shared__ __align__(16) char smem[];
    const uint32_t sb = s2u(smem);
    const int tid = threadIdx.x;
    const int lane = tid & 31, wid = tid >> 5;
    const int n0 = blockIdx.x * QT;
    const int b  = blockIdx.y;

    const char* qg = (const char*)(g_q + ((size_t)b * NPOS + n0) * CH);
    const char* kg = (const char*)(g_k + (size_t)b * NPOS * CH);
    const char* vg = (const char*)(g_v + (size_t)b * NPOS * CH);

#pragma unroll
    for (int it = 0; it < 16; it++) {
        const int g = tid + it * 256;
        const int row = g >> 5, ch = g & 31;
        cpa16(sb + QO + row * RS + ch * 16, qg + row * 512 + ch * 16);
    }
#pragma unroll
    for (int it = 0; it < 8; it++) {
        const int g = tid + it * 256;
        const int row = g >> 5, ch = g & 31;
        cpa16(sb + KO + row * RS + ch * 16, kg + row * 512 + ch * 16);
        cpa16(sb + VO + row * RS + ch * 16, vg + row * 512 + ch * 16);
    }
    cp_commit();

    const uint32_t lrow = (lane & 15);
    const uint32_t lcol = (lane >> 4) << 4;
    const uint32_t aB = sb + QO + (wid * 16 + lrow) * RS + lcol;
    const uint32_t kB = sb + KO + lrow * RS + lcol;
    const uint32_t vB = sb + VO + lrow * RS + lcol;

    // O accumulators: packed f16. o2[t][0] = row r, cols {c, c+1}; o2[t][1] = row r+8.
    uint32_t o2[32][2];
#pragma unroll
    for (int t = 0; t < 32; t++) { o2[t][0] = 0u; o2[t][1] = 0u; }
    float m0 = -1e30f, m1 = -1e30f, l0 = 0.f, l1 = 0.f;

    for (int kt = 0; kt < NKT; kt++) {
        const uint32_t buf = (kt & 1) * KVB;
        if (kt > 0) __syncthreads();
        if (kt + 1 < NKT) {
            const uint32_t nbuf = ((kt + 1) & 1) * KVB;
            const char* kgt = kg + (size_t)(kt + 1) * KTILE * 512;
            const char* vgt = vg + (size_t)(kt + 1) * KTILE * 512;
#pragma unroll
            for (int it = 0; it < 8; it++) {
                const int g = tid + it * 256;
                const int row = g >> 5, ch = g & 31;
                cpa16(sb + KO + nbuf + row * RS + ch * 16, kgt + row * 512 + ch * 16);
                cpa16(sb + VO + nbuf + row * RS + ch * 16, vgt + row * 512 + ch * 16);
            }
            cp_commit();
            cp_wait<1>();
        } else {
            cp_wait<0>();
        }
        __syncthreads();

        // ---- S = Q K^T ----
        float s[8][4];
#pragma unroll
        for (int t = 0; t < 8; t++)
#pragma unroll
            for (int u = 0; u < 4; u++) s[t][u] = 0.f;

#pragma unroll 4
        for (int cs = 0; cs < 16; cs++) {
            uint32_t a[4];
            ldsm4(a, aB + cs * 32);
#pragma unroll
            for (int k16 = 0; k16 < 4; k16++) {
                uint32_t kr[4];
                ldsm4(kr, kB + buf + k16 * (16 * RS) + cs * 32);
                mma16816(s[2 * k16 + 0], a, kr[0], kr[2]);
                mma16816(s[2 * k16 + 1], a, kr[1], kr[3]);
            }
        }

        // ---- online softmax ----
        float mt0 = s[0][0], mt1 = s[0][2];
#pragma unroll
        for (int t = 0; t < 8; t++) {
            mt0 = fmaxf(mt0, fmaxf(s[t][0], s[t][1]));
            mt1 = fmaxf(mt1, fmaxf(s[t][2], s[t][3]));
        }
        mt0 = fmaxf(mt0, __shfl_xor_sync(~0u, mt0, 1));
        mt0 = fmaxf(mt0, __shfl_xor_sync(~0u, mt0, 2));
        mt1 = fmaxf(mt1, __shfl_xor_sync(~0u, mt1, 1));
        mt1 = fmaxf(mt1, __shfl_xor_sync(~0u, mt1, 2));

        const float mn0 = fmaxf(m0, mt0), mn1 = fmaxf(m1, mt1);
        if (mn0 > m0 || mn1 > m1) {
            const float sc0 = ex2((m0 - mn0) * L2E);
            const float sc1 = ex2((m1 - mn1) * L2E);
            l0 *= sc0; l1 *= sc1;
            const __half2 sh0 = __float2half2_rn(sc0);
            const __half2 sh1 = __float2half2_rn(sc1);
#pragma unroll
            for (int t = 0; t < 32; t++) {
                __half2 u0 = *(__half2*)&o2[t][0];
                __half2 u1 = *(__half2*)&o2[t][1];
                u0 = __hmul2(u0, sh0);
                u1 = __hmul2(u1, sh1);
                o2[t][0] = *(const uint32_t*)&u0;
                o2[t][1] = *(const uint32_t*)&u1;
            }
            m0 = mn0; m1 = mn1;
        }
        const float mL0 = m0 * L2E, mL1 = m1 * L2E;
        float ps0 = 0.f, ps1 = 0.f;
#pragma unroll
        for (int t = 0; t < 8; t++) {
            s[t][0] = ex2(fmaf(s[t][0], L2E, -mL0));
            s[t][1] = ex2(fmaf(s[t][1], L2E, -mL0));
            s[t][2] = ex2(fmaf(s[t][2], L2E, -mL1));
            s[t][3] = ex2(fmaf(s[t][3], L2E, -mL1));
            ps0 += s[t][0] + s[t][1];
            ps1 += s[t][2] + s[t][3];
        }
        l0 += ps0; l1 += ps1;

        // ---- O += P V  (f16 x f16 -> f16) ----
#pragma unroll
        for (int js = 0; js < 4; js++) {
            uint32_t pa[4];
            {
                const __half2 h0 = __floats2half2_rn(s[2 * js][0], s[2 * js][1]);
                const __half2 h1 = __floats2half2_rn(s[2 * js][2], s[2 * js][3]);
                const __half2 h2 = __floats2half2_rn(s[2 * js + 1][0], s[2 * js + 1][1]);
                const __half2 h3 = __floats2half2_rn(s[2 * js + 1][2], s[2 * js + 1][3]);
                pa[0] = *(const uint32_t*)&h0;
                pa[1] = *(const uint32_t*)&h1;
                pa[2] = *(const uint32_t*)&h2;
                pa[3] = *(const uint32_t*)&h3;
            }
#pragma unroll
            for (int cp = 0; cp < 16; cp++) {
                uint32_t vr[4];
                ldsm4t(vr, vB + buf + js * (16 * RS) + cp * 32);
                mma16816h(o2[2 * cp + 0], pa, vr[0], vr[1]);
                mma16816h(o2[2 * cp + 1], pa, vr[2], vr[3]);
            }
        }
    }

    // ---- epilogue ----
    l0 += __shfl_xor_sync(~0u, l0, 1);
    l0 += __shfl_xor_sync(~0u, l0, 2);
    l1 += __shfl_xor_sync(~0u, l1, 1);
    l1 += __shfl_xor_sync(~0u, l1, 2);
    const float g0 = gamma[0];
    const float e0 = g0 / (l0 * 64.0f);          // sqrt(4096) = 64
    const float e1 = g0 / (l1 * 64.0f);
    const int nrow = n0 + wid * 16 + (lane >> 2);
#pragma unroll
    for (int t = 0; t < 32; t++) {
        const int c = t * 8 + 2 * (lane & 3);
        const size_t i0 = ((size_t)b * CH + c) * NPOS + nrow;
        const __half2 u0 = *(const __half2*)&o2[t][0];   // row r:   {c, c+1}
        const __half2 u1 = *(const __half2*)&o2[t][1];   // row r+8: {c, c+1}
        out[i0]            = __low2float(u0)  * e0 + x[i0];
        out[i0 + NPOS]     = __high2float(u0) * e0 + x[i0 + NPOS];
        out[i0 + 8]        = __low2float(u1)  * e1 + x[i0 + 8];
        out[i0 + NPOS + 8] = __high2float(u1) * e1 + x[i0 + NPOS + 8];
    }
}

// ---------------------------------------------------------------------------
extern "C" void kernel_launch(void* const* d_in, const int* in_sizes, int n_in,
                              void* d_out, int out_size)
{
    const float* x     = (const float*)d_in[0];
    const float* Wq    = (const float*)d_in[1];
    const float* bq    = (const float*)d_in[2];
    const float* Wk    = (const float*)d_in[3];
    const float* bk    = (const float*)d_in[4];
    const float* Wv    = (const float*)d_in[5];
    const float* bv    = (const float*)d_in[6];
    const float* gamma = (const float*)d_in[7];
    float* out = (float*)d_out;

    cudaFuncSetAttribute(qkv_mma_kernel, cudaFuncAttributeMaxDynamicSharedMemorySize, QKV_SMEM);
    cudaFuncSetAttribute(attn_kernel,    cudaFuncAttributeMaxDynamicSharedMemorySize, ATTN_SMEM);

    convert_kernel<<<1024, 256>>>(x, Wq, Wk, Wv);
    qkv_mma_kernel<<<dim3(NPOS / QT, BATCH, 3), 256, QKV_SMEM>>>(bq, bk, bv);
    attn_kernel<<<dim3(NPOS / QT, BATCH), 256, ATTN_SMEM>>>(x, gamma, out);
}